// round 8
// baseline (speedup 1.0000x reference)
#include <cuda_runtime.h>
#include <stdint.h>

// B=16, N=2048.
__device__ unsigned char g_keep[16 * 2048];   // keep[b][n]
__device__ int           g_ready[16];         // per-batch release flag (memset 0 per launch)

__device__ __forceinline__ unsigned orderable(float f) {
    unsigned x = __float_as_uint(f);
    return x ^ ((x & 0x80000000u) ? 0xFFFFFFFFu : 0x80000000u);
}

// ---------------------------------------------------------------------------
// Fused kernel, 1 row per block. Grid = B*N, 256 threads, <=32 regs (forced).
//  - all blocks: prefetch their 2 float4 of adj (loads in flight)
//  - blocks 0..B-1: 8-bit radix select for batch=bid, NO score cache in smem
//    (scores re-read from L2 each level; smem = hist only, ~1.3KB).
//    Bit-exact jax.lax.top_k selection (value desc, ties -> lower index).
//  - all blocks: spin on g_ready[batch], then apply row/col union mask.
// Deadlock-free: bids 0..15 are wave-1 resident (grid >> 148, low bids first).
// ---------------------------------------------------------------------------
__global__ void __launch_bounds__(256, 8)
fused_topk_mask_kernel(const float4* __restrict__ adj,
                       const float*  __restrict__ score,
                       float4* __restrict__ out, int N, int k, int B) {
    const int tid  = threadIdx.x;
    const int nvec = N >> 2;                  // 512
    int row = blockIdx.x;                     // 0 .. B*N-1
    int b   = row / N;
    int i   = row - b * N;

    size_t base = (size_t)row * nvec;
    int j0 = tid, j1 = tid + 256;             // nvec = 512 exactly

    // ---- prefetch: 2 front-batched global loads ----
    float4 v0 = adj[base + j0];
    float4 v1 = adj[base + j1];

    // ---- blocks 0..B-1: top-k radix select (smem = hist only) ----
    if (blockIdx.x < (unsigned)B) {
        __shared__ unsigned hist[256];
        __shared__ unsigned s_prefix, s_kk;

        const int bb = blockIdx.x;
        const float* sc = score + (size_t)bb * N;

        if (tid == 0) { s_prefix = 0u; s_kk = (unsigned)k; }
        __syncthreads();

        for (int shift = 24; shift >= 0; shift -= 8) {
            const unsigned prefix = s_prefix;
            const unsigned kk     = s_kk;
            const unsigned pmask  = (shift == 24) ? 0u
                                                  : (0xFFFFFFFFu << (shift + 8));
            hist[tid] = 0u;
            __syncthreads();

            for (int t = tid; t < N; t += 256) {
                unsigned x = orderable(__ldg(&sc[t]));
                if ((x & pmask) == prefix)
                    atomicAdd(&hist[(x >> shift) & 0xFFu], 1u);
            }
            __syncthreads();

            // single-warp suffix scan over 256 bins
            if (tid < 32) {
                unsigned v[8], p[8];
                unsigned acc = 0u;
#pragma unroll
                for (int q = 0; q < 8; q++) {
                    v[q] = hist[255 - (tid * 8 + q)];
                    acc += v[q];
                    p[q] = acc;
                }
                unsigned lane_excl = 0u, run = acc;
#pragma unroll
                for (int off = 1; off < 32; off <<= 1) {
                    unsigned n0 = __shfl_up_sync(0xFFFFFFFFu, run, off);
                    if (tid >= off) { lane_excl += n0; run += n0; }
                }
#pragma unroll
                for (int q = 0; q < 8; q++) {
                    unsigned incl = lane_excl + p[q];
                    unsigned excl = incl - v[q];
                    if (excl < kk && incl >= kk) {          // unique bin
                        int bin = 255 - (tid * 8 + q);
                        s_prefix = prefix | ((unsigned)bin << shift);
                        s_kk     = kk - excl;
                    }
                }
            }
            __syncthreads();
        }

        const unsigned T        = s_prefix;        // exact k-th largest pattern
        const unsigned need_eq  = s_kk;            // equals to keep (>=1)
        const unsigned total_eq = hist[T & 0xFFu]; // exact equal count

        for (int t = tid; t < N; t += 256) {
            unsigned x = orderable(__ldg(&sc[t]));
            unsigned char kp = 0u;
            if (x > T) {
                kp = 1u;
            } else if (x == T) {
                if (total_eq == need_eq) {
                    kp = 1u;                       // common path: keep all equals
                } else {
                    unsigned c = 0u;               // rare tie path: rank by index
                    for (int j = 0; j < t; j++)
                        c += (orderable(__ldg(&sc[j])) == T);
                    kp = (c < need_eq) ? 1u : 0u;
                }
            }
            g_keep[bb * N + t] = kp;
        }

        __threadfence();
        __syncthreads();
        if (tid == 0) ((volatile int*)g_ready)[bb] = 1;
    }

    // ---- wait for this batch's keep mask (overlaps in-flight loads) ----
    if (tid == 0) {
        while (((volatile int*)g_ready)[b] == 0) __nanosleep(64);
    }
    __syncthreads();
    __threadfence();

    const unsigned char* kb = g_keep + b * N;
    const uchar4*        km = (const uchar4*)kb;   // 2KB, L1/L2-resident
    bool row_kept = (kb[i] != 0);

    if (!row_kept) {
        uchar4 m0 = km[j0];
        uchar4 m1 = km[j1];
        v0.x = m0.x ? v0.x : 0.0f;  v0.y = m0.y ? v0.y : 0.0f;
        v0.z = m0.z ? v0.z : 0.0f;  v0.w = m0.w ? v0.w : 0.0f;
        v1.x = m1.x ? v1.x : 0.0f;  v1.y = m1.y ? v1.y : 0.0f;
        v1.z = m1.z ? v1.z : 0.0f;  v1.w = m1.w ? v1.w : 0.0f;
    }
    out[base + j0] = v0;
    out[base + j1] = v1;
}

extern "C" void kernel_launch(void* const* d_in, const int* in_sizes, int n_in,
                              void* d_out, int out_size) {
    const float* adj   = (const float*)d_in[0];   // [B, N, N] fp32
    const float* score = (const float*)d_in[1];   // [B, N, 1] fp32

    long long n_adj   = in_sizes[0];
    long long n_score = in_sizes[1];
    int N = (int)(n_adj / n_score);               // 2048
    int B = (int)(n_score / N);                   // 16
    int k = N / 2;                                // RATE = 0.5

    // clear release flags (graph-capturable memset node, no allocation)
    void* flags = nullptr;
    cudaGetSymbolAddress(&flags, g_ready);
    cudaMemsetAsync(flags, 0, sizeof(int) * 16, 0);

    fused_topk_mask_kernel<<<B * N, 256>>>(
        (const float4*)adj, score, (float4*)d_out, N, k, B);
}

// round 9
// speedup vs baseline: 1.0356x; 1.0356x over previous
#include <cuda_runtime.h>
#include <stdint.h>

// B=16, N=2048.
__device__ unsigned char g_keep[16 * 2048];   // keep[b][n]
__device__ unsigned      g_ready[16];         // per-batch release flag (memset 0 per launch)

__device__ __forceinline__ unsigned orderable(float f) {
    unsigned x = __float_as_uint(f);
    return x ^ ((x & 0x80000000u) ? 0xFFFFFFFFu : 0x80000000u);
}

// ---------------------------------------------------------------------------
// Fused kernel, 1 row per block. Grid = B*N, 256 threads.
//  - all blocks: prefetch their 2 float4 of adj (loads in flight)
//  - blocks 0..B-1: exact 8-bit radix select for batch=bid (smem-cached
//    scores, warp-shfl bin scan). Bit-exact jax.lax.top_k selection.
//    Publish g_keep, __threadfence (16 blocks only), st.release flag.
//  - all blocks: spin with ld.acquire.gpu (NO L1 flush), read mask via __ldcg.
// Deadlock-free: bids 0..15 are wave-1 resident; they spin on flags produced
// by blocks 0..15 which never wait before publishing.
// ---------------------------------------------------------------------------
__global__ void __launch_bounds__(256, 8)
fused_topk_mask_kernel(const float4* __restrict__ adj,
                       const float*  __restrict__ score,
                       float4* __restrict__ out, int N, int k, int B) {
    const int tid  = threadIdx.x;
    const int nvec = N >> 2;                  // 512
    int row = blockIdx.x;                     // 0 .. B*N-1
    int b   = row / N;
    int i   = row - b * N;

    size_t base = (size_t)row * nvec;
    int j0 = tid, j1 = tid + 256;             // nvec = 512 exactly

    // ---- prefetch: 2 front-batched global loads (held across the wait) ----
    float4 v0 = adj[base + j0];
    float4 v1 = adj[base + j1];

    // ---- blocks 0..B-1: top-k radix select ----
    if (blockIdx.x < (unsigned)B) {
        __shared__ unsigned u[2048];
        __shared__ unsigned hist[256];
        __shared__ unsigned s_prefix, s_kk;

        const int bb = blockIdx.x;
        const float* sc = score + (size_t)bb * N;

        for (int t = tid; t < N; t += 256) u[t] = orderable(sc[t]);
        if (tid == 0) { s_prefix = 0u; s_kk = (unsigned)k; }
        __syncthreads();

        for (int shift = 24; shift >= 0; shift -= 8) {
            const unsigned prefix = s_prefix;
            const unsigned kk     = s_kk;
            const unsigned pmask  = (shift == 24) ? 0u
                                                  : (0xFFFFFFFFu << (shift + 8));
            hist[tid] = 0u;
            __syncthreads();
            for (int t = tid; t < N; t += 256) {
                unsigned x = u[t];
                if ((x & pmask) == prefix)
                    atomicAdd(&hist[(x >> shift) & 0xFFu], 1u);
            }
            __syncthreads();

            // single-warp suffix scan over 256 bins
            if (tid < 32) {
                unsigned v[8], p[8];
                unsigned acc = 0u;
#pragma unroll
                for (int q = 0; q < 8; q++) {
                    v[q] = hist[255 - (tid * 8 + q)];
                    acc += v[q];
                    p[q] = acc;
                }
                unsigned lane_excl = 0u, run = acc;
#pragma unroll
                for (int off = 1; off < 32; off <<= 1) {
                    unsigned n0 = __shfl_up_sync(0xFFFFFFFFu, run, off);
                    if (tid >= off) { lane_excl += n0; run += n0; }
                }
#pragma unroll
                for (int q = 0; q < 8; q++) {
                    unsigned incl = lane_excl + p[q];
                    unsigned excl = incl - v[q];
                    if (excl < kk && incl >= kk) {          // unique bin
                        int bin = 255 - (tid * 8 + q);
                        s_prefix = prefix | ((unsigned)bin << shift);
                        s_kk     = kk - excl;
                    }
                }
            }
            __syncthreads();
        }

        const unsigned T        = s_prefix;        // exact k-th largest pattern
        const unsigned need_eq  = s_kk;            // equals to keep (>=1)
        const unsigned total_eq = hist[T & 0xFFu]; // exact equal count

        for (int t = tid; t < N; t += 256) {
            unsigned x = u[t];
            unsigned char kp = 0u;
            if (x > T) {
                kp = 1u;
            } else if (x == T) {
                if (total_eq == need_eq) {
                    kp = 1u;                       // common: keep all equals
                } else {
                    unsigned c = 0u;               // rare: rank ties by index
                    for (int j = 0; j < t; j++) c += (u[j] == T);
                    kp = (c < need_eq) ? 1u : 0u;
                }
            }
            g_keep[bb * N + t] = kp;
        }

        __threadfence();                           // producer-side only (16 blocks)
        __syncthreads();
        if (tid == 0) {
            asm volatile("st.release.gpu.global.u32 [%0], %1;"
                         :: "l"(&g_ready[bb]), "r"(1u) : "memory");
        }
    }

    // ---- wait for this batch's flag: acquire load, NO L1 flush ----
    if (tid == 0) {
        unsigned f;
        do {
            asm volatile("ld.acquire.gpu.global.u32 %0, [%1];"
                         : "=r"(f) : "l"(&g_ready[b]) : "memory");
            if (!f) __nanosleep(64);
        } while (!f);
    }
    __syncthreads();

    // mask reads via L2 (__ldcg): coherent with producer's threadfence,
    // bypasses (unflushed) L1.
    const uchar4* km = (const uchar4*)(g_keep + b * N);
    uchar4 mrow = __ldcg(&km[i >> 2]);
    unsigned char rowflag = (i & 3) == 0 ? mrow.x :
                            (i & 3) == 1 ? mrow.y :
                            (i & 3) == 2 ? mrow.z : mrow.w;

    if (!rowflag) {
        uchar4 m0 = __ldcg(&km[j0]);
        uchar4 m1 = __ldcg(&km[j1]);
        v0.x = m0.x ? v0.x : 0.0f;  v0.y = m0.y ? v0.y : 0.0f;
        v0.z = m0.z ? v0.z : 0.0f;  v0.w = m0.w ? v0.w : 0.0f;
        v1.x = m1.x ? v1.x : 0.0f;  v1.y = m1.y ? v1.y : 0.0f;
        v1.z = m1.z ? v1.z : 0.0f;  v1.w = m1.w ? v1.w : 0.0f;
    }
    out[base + j0] = v0;
    out[base + j1] = v1;
}

extern "C" void kernel_launch(void* const* d_in, const int* in_sizes, int n_in,
                              void* d_out, int out_size) {
    const float* adj   = (const float*)d_in[0];   // [B, N, N] fp32
    const float* score = (const float*)d_in[1];   // [B, N, 1] fp32

    long long n_adj   = in_sizes[0];
    long long n_score = in_sizes[1];
    int N = (int)(n_adj / n_score);               // 2048
    int B = (int)(n_score / N);                   // 16
    int k = N / 2;                                // RATE = 0.5

    // clear release flags (graph-capturable memset node, no allocation)
    void* flags = nullptr;
    cudaGetSymbolAddress(&flags, g_ready);
    cudaMemsetAsync(flags, 0, sizeof(unsigned) * 16, 0);

    fused_topk_mask_kernel<<<B * N, 256>>>(
        (const float4*)adj, score, (float4*)d_out, N, k, B);
}

// round 10
// speedup vs baseline: 1.3162x; 1.2710x over previous
#include <cuda_runtime.h>
#include <stdint.h>

// B=16, N=2048.
__device__ unsigned char g_keep[16 * 2048];   // keep[b][n]
__device__ unsigned      g_ready[16];         // per-batch release flag (memset 0 per launch)

__device__ __forceinline__ unsigned orderable(float f) {
    unsigned x = __float_as_uint(f);
    return x ^ ((x & 0x80000000u) ? 0xFFFFFFFFu : 0x80000000u);
}

// ---------------------------------------------------------------------------
// Fused kernel, 1 row per block. Grid = B*N, 256 threads.
// NO register cap (R8/R9 forced <=32 regs -> local-memory spills -> DRAM 53%).
// NO consumer threadfence (R5's CCTL.IVALL L1 flush per block -> DRAM 71%).
//  - all blocks: prefetch their 2 float4 of adj (loads in flight)
//  - blocks 0..B-1: exact 8-bit radix select for batch=bid (smem score cache,
//    warp-shfl bin scan). Bit-exact jax.lax.top_k (value desc, ties->low idx).
//    Publish g_keep, __threadfence (16 blocks only), st.release flag.
//  - all blocks: spin with ld.acquire.gpu, read mask via __ldcg (L2 path).
// Deadlock-free: bids 0..15 are wave-1 resident and publish before waiting.
// ---------------------------------------------------------------------------
__global__ void __launch_bounds__(256)
fused_topk_mask_kernel(const float4* __restrict__ adj,
                       const float*  __restrict__ score,
                       float4* __restrict__ out, int N, int k, int B) {
    const int tid  = threadIdx.x;
    const int nvec = N >> 2;                  // 512
    int row = blockIdx.x;                     // 0 .. B*N-1
    int b   = row / N;
    int i   = row - b * N;

    size_t base = (size_t)row * nvec;
    int j0 = tid, j1 = tid + 256;             // nvec = 512 exactly

    // ---- prefetch: 2 front-batched global loads (held across the wait) ----
    float4 v0 = adj[base + j0];
    float4 v1 = adj[base + j1];

    // ---- blocks 0..B-1: top-k radix select ----
    if (blockIdx.x < (unsigned)B) {
        __shared__ unsigned u[2048];
        __shared__ unsigned hist[256];
        __shared__ unsigned s_prefix, s_kk;

        const int bb = blockIdx.x;
        const float* sc = score + (size_t)bb * N;

        for (int t = tid; t < N; t += 256) u[t] = orderable(sc[t]);
        if (tid == 0) { s_prefix = 0u; s_kk = (unsigned)k; }
        __syncthreads();

        for (int shift = 24; shift >= 0; shift -= 8) {
            const unsigned prefix = s_prefix;
            const unsigned kk     = s_kk;
            const unsigned pmask  = (shift == 24) ? 0u
                                                  : (0xFFFFFFFFu << (shift + 8));
            hist[tid] = 0u;
            __syncthreads();
            for (int t = tid; t < N; t += 256) {
                unsigned x = u[t];
                if ((x & pmask) == prefix)
                    atomicAdd(&hist[(x >> shift) & 0xFFu], 1u);
            }
            __syncthreads();

            // single-warp suffix scan over 256 bins
            if (tid < 32) {
                unsigned v[8], p[8];
                unsigned acc = 0u;
#pragma unroll
                for (int q = 0; q < 8; q++) {
                    v[q] = hist[255 - (tid * 8 + q)];
                    acc += v[q];
                    p[q] = acc;
                }
                unsigned lane_excl = 0u, run = acc;
#pragma unroll
                for (int off = 1; off < 32; off <<= 1) {
                    unsigned n0 = __shfl_up_sync(0xFFFFFFFFu, run, off);
                    if (tid >= off) { lane_excl += n0; run += n0; }
                }
#pragma unroll
                for (int q = 0; q < 8; q++) {
                    unsigned incl = lane_excl + p[q];
                    unsigned excl = incl - v[q];
                    if (excl < kk && incl >= kk) {          // unique bin
                        int bin = 255 - (tid * 8 + q);
                        s_prefix = prefix | ((unsigned)bin << shift);
                        s_kk     = kk - excl;
                    }
                }
            }
            __syncthreads();
        }

        const unsigned T        = s_prefix;        // exact k-th largest pattern
        const unsigned need_eq  = s_kk;            // equals to keep (>=1)
        const unsigned total_eq = hist[T & 0xFFu]; // exact equal count

        for (int t = tid; t < N; t += 256) {
            unsigned x = u[t];
            unsigned char kp = 0u;
            if (x > T) {
                kp = 1u;
            } else if (x == T) {
                if (total_eq == need_eq) {
                    kp = 1u;                       // common: keep all equals
                } else {
                    unsigned c = 0u;               // rare: rank ties by index
                    for (int j = 0; j < t; j++) c += (u[j] == T);
                    kp = (c < need_eq) ? 1u : 0u;
                }
            }
            g_keep[bb * N + t] = kp;
        }

        __threadfence();                           // producer-side only (16 blocks)
        __syncthreads();
        if (tid == 0) {
            asm volatile("st.release.gpu.global.u32 [%0], %1;"
                         :: "l"(&g_ready[bb]), "r"(1u) : "memory");
        }
    }

    // ---- wait for this batch's flag: acquire load, NO L1 flush ----
    if (tid == 0) {
        unsigned f;
        do {
            asm volatile("ld.acquire.gpu.global.u32 %0, [%1];"
                         : "=r"(f) : "l"(&g_ready[b]) : "memory");
            if (!f) __nanosleep(64);
        } while (!f);
    }
    __syncthreads();

    // mask reads via L2 (__ldcg): coherent with producer's threadfence.
    const uchar4* km = (const uchar4*)(g_keep + b * N);
    uchar4 mrow = __ldcg(&km[i >> 2]);
    unsigned char rowflag = (i & 3) == 0 ? mrow.x :
                            (i & 3) == 1 ? mrow.y :
                            (i & 3) == 2 ? mrow.z : mrow.w;

    if (!rowflag) {
        uchar4 m0 = __ldcg(&km[j0]);
        uchar4 m1 = __ldcg(&km[j1]);
        v0.x = m0.x ? v0.x : 0.0f;  v0.y = m0.y ? v0.y : 0.0f;
        v0.z = m0.z ? v0.z : 0.0f;  v0.w = m0.w ? v0.w : 0.0f;
        v1.x = m1.x ? v1.x : 0.0f;  v1.y = m1.y ? v1.y : 0.0f;
        v1.z = m1.z ? v1.z : 0.0f;  v1.w = m1.w ? v1.w : 0.0f;
    }
    out[base + j0] = v0;
    out[base + j1] = v1;
}

extern "C" void kernel_launch(void* const* d_in, const int* in_sizes, int n_in,
                              void* d_out, int out_size) {
    const float* adj   = (const float*)d_in[0];   // [B, N, N] fp32
    const float* score = (const float*)d_in[1];   // [B, N, 1] fp32

    long long n_adj   = in_sizes[0];
    long long n_score = in_sizes[1];
    int N = (int)(n_adj / n_score);               // 2048
    int B = (int)(n_score / N);                   // 16
    int k = N / 2;                                // RATE = 0.5

    // clear release flags (graph-capturable memset node, no allocation)
    void* flags = nullptr;
    cudaGetSymbolAddress(&flags, g_ready);
    cudaMemsetAsync(flags, 0, sizeof(unsigned) * 16, 0);

    fused_topk_mask_kernel<<<B * N, 256>>>(
        (const float4*)adj, score, (float4*)d_out, N, k, B);
}

// round 11
// speedup vs baseline: 1.4288x; 1.0855x over previous
#include <cuda_runtime.h>
#include <stdint.h>

// keep[b][n] = 1 if node n is in the top-k of batch b. B=16, N=2048.
__device__ unsigned char g_keep[16 * 2048];

// ---------------------------------------------------------------------------
// Kernel 1: exact top-k via 8-bit radix select.
// Bin suffix-scan by ONE WARP with shfl (no block barriers in the scan).
// Keep set: u > T, plus need_eq lowest-index elements with u == T.
// Bit-exact vs jax.lax.top_k (value desc, ties -> lower index).
// One block per batch, 256 threads. Ends with PDL trigger.
// ---------------------------------------------------------------------------
__global__ void __launch_bounds__(256)
topk_radix_kernel(const float* __restrict__ score, int N, int k) {
    __shared__ unsigned u[2048];
    __shared__ unsigned hist[256];
    __shared__ unsigned s_prefix, s_kk;

    const int b   = blockIdx.x;
    const int tid = threadIdx.x;
    const float* sc = score + (size_t)b * N;

    for (int t = tid; t < N; t += 256) {
        unsigned x = __float_as_uint(sc[t]);
        x ^= (x & 0x80000000u) ? 0xFFFFFFFFu : 0x80000000u;  // order-preserving
        u[t] = x;
    }
    if (tid == 0) { s_prefix = 0u; s_kk = (unsigned)k; }
    __syncthreads();

    for (int shift = 24; shift >= 0; shift -= 8) {
        const unsigned prefix = s_prefix;
        const unsigned kk     = s_kk;
        const unsigned pmask  = (shift == 24) ? 0u : (0xFFFFFFFFu << (shift + 8));

        hist[tid] = 0u;
        __syncthreads();

        for (int t = tid; t < N; t += 256) {
            unsigned x = u[t];
            if ((x & pmask) == prefix)
                atomicAdd(&hist[(x >> shift) & 0xFFu], 1u);
        }
        __syncthreads();

        // single-warp suffix scan over 256 bins: r = 255 - bin
        if (tid < 32) {
            unsigned v[8], p[8];
            unsigned acc = 0u;
#pragma unroll
            for (int i = 0; i < 8; i++) {
                v[i] = hist[255 - (tid * 8 + i)];
                acc += v[i];
                p[i] = acc;                       // lane-local inclusive prefix
            }
            unsigned lane_excl = 0u, run = acc;
#pragma unroll
            for (int off = 1; off < 32; off <<= 1) {
                unsigned n0 = __shfl_up_sync(0xFFFFFFFFu, run, off);
                if ((int)(tid) >= off) { lane_excl += n0; run += n0; }
            }
#pragma unroll
            for (int i = 0; i < 8; i++) {
                unsigned incl = lane_excl + p[i];
                unsigned excl = incl - v[i];
                if (excl < kk && incl >= kk) {    // unique r
                    int bin = 255 - (tid * 8 + i);
                    s_prefix = prefix | ((unsigned)bin << shift);
                    s_kk     = kk - excl;
                }
            }
        }
        __syncthreads();
    }

    const unsigned T        = s_prefix;          // exact k-th largest pattern
    const unsigned need_eq  = s_kk;              // equals to keep (>=1)
    const unsigned total_eq = hist[T & 0xFFu];   // exact equal count (last level)

    for (int t = tid; t < N; t += 256) {
        unsigned x = u[t];
        unsigned char kp = 0u;
        if (x > T) {
            kp = 1u;
        } else if (x == T) {
            if (total_eq == need_eq) {
                kp = 1u;                         // common path: keep all equals
            } else {
                unsigned c = 0u;                 // rare: rank among equals by index
                for (int j = 0; j < t; j++) c += (u[j] == T);
                kp = (c < need_eq) ? 1u : 0u;
            }
        }
        g_keep[b * N + t] = kp;
    }

    __threadfence();
    __syncthreads();
    if (tid == 0) cudaTriggerProgrammaticLaunchCompletion();
}

// ---------------------------------------------------------------------------
// Kernel 2: out[b,i,j] = adj[b,i,j] * (keep[b,i] || keep[b,j])
// PDL secondary (R6 shape: 76.3us @ 79.6% DRAM, 32 regs): prefetch adj BEFORE
// cudaGridDependencySynchronize() so launch latency + wave-1 loads overlap topk.
// ---------------------------------------------------------------------------
__global__ void apply_mask_kernel(const float4* __restrict__ adj,
                                  float4* __restrict__ out, int N) {
    int row = blockIdx.x;              // 0 .. B*N-1
    int b   = row / N;
    int i   = row - b * N;

    int    nvec = N >> 2;
    size_t base = (size_t)row * nvec;

    int  j0 = threadIdx.x;
    int  j1 = threadIdx.x + blockDim.x;
    bool h0 = j0 < nvec;
    bool h1 = j1 < nvec;

    float4 v0 = {0,0,0,0}, v1 = {0,0,0,0};
    if (h0) v0 = adj[base + j0];
    if (h1) v1 = adj[base + j1];

    cudaGridDependencySynchronize();   // wait for g_keep (overlapped w/ loads)

    const unsigned char* kb = g_keep + b * N;
    const uchar4*        km = (const uchar4*)kb;  // 2KB, L1-resident
    bool row_kept = (kb[i] != 0);

    if (!row_kept) {
        if (h0) {
            uchar4 m = km[j0];
            v0.x = m.x ? v0.x : 0.0f;  v0.y = m.y ? v0.y : 0.0f;
            v0.z = m.z ? v0.z : 0.0f;  v0.w = m.w ? v0.w : 0.0f;
        }
        if (h1) {
            uchar4 m = km[j1];
            v1.x = m.x ? v1.x : 0.0f;  v1.y = m.y ? v1.y : 0.0f;
            v1.z = m.z ? v1.z : 0.0f;  v1.w = m.w ? v1.w : 0.0f;
        }
    }
    if (h0) out[base + j0] = v0;
    if (h1) out[base + j1] = v1;

    // generic tail (unused for N=2048 with 256 threads)
    for (int j = threadIdx.x + 2 * blockDim.x; j < nvec; j += blockDim.x) {
        float4 v = adj[base + j];
        if (!row_kept) {
            uchar4 m = km[j];
            v.x = m.x ? v.x : 0.0f;  v.y = m.y ? v.y : 0.0f;
            v.z = m.z ? v.z : 0.0f;  v.w = m.w ? v.w : 0.0f;
        }
        out[base + j] = v;
    }
}

extern "C" void kernel_launch(void* const* d_in, const int* in_sizes, int n_in,
                              void* d_out, int out_size) {
    const float* adj   = (const float*)d_in[0];   // [B, N, N] fp32
    const float* score = (const float*)d_in[1];   // [B, N, 1] fp32

    long long n_adj   = in_sizes[0];
    long long n_score = in_sizes[1];
    int N = (int)(n_adj / n_score);               // 2048
    int B = (int)(n_score / N);                   // 16
    int k = N / 2;                                // RATE = 0.5

    topk_radix_kernel<<<B, 256>>>(score, N, k);

    // Secondary with Programmatic Stream Serialization (PDL).
    cudaLaunchConfig_t cfg = {};
    cfg.gridDim  = dim3((unsigned)(B * N));
    cfg.blockDim = dim3(256);
    cfg.stream   = 0;
    cudaLaunchAttribute attr[1];
    attr[0].id = cudaLaunchAttributeProgrammaticStreamSerialization;
    attr[0].val.programmaticStreamSerializationAllowed = 1;
    cfg.attrs    = attr;
    cfg.numAttrs = 1;
    cudaLaunchKernelEx(&cfg, apply_mask_kernel,
                       (const float4*)adj, (float4*)d_out, N);
}